// round 12
// baseline (speedup 1.0000x reference)
#include <cuda_runtime.h>
#include <cuda_fp16.h>
#include <cstdint>
#include <math.h>

#define BB   512
#define SS   200
#define DD   1024
#define PP   256
#define G4   4096
#define DIN  1280
#define NCTA 128
#define NGRP 32    // CTAs per m-group barrier

#define WG_U32 17408   // gates weight slice per CTA in u32 (17*4*2*32*4)
#define WP_U32 16384   // proj weight slice per CTA in u32 (4*64*64)
#define ZC_F32 16384   // Zc tile (128 x 128)
#define SMEM_BYTES ((WG_U32 + WP_U32) * 4 + ZC_F32 * 4)

// ---------------- scratch (device globals; no allocation allowed) ----------------
__device__ float g_bias[G4];                       // folded bias
__device__ float g_Zc[(size_t)BB * G4];            // (512,4096) context+bias
__device__ float g_hs[(size_t)BB * SS * PP];       // all projected hiddens (heads)
__device__ unsigned int g_bar_cnt[4 * 32];         // per-m-group barrier counters (128B apart)

// gates weights, fragment-packed fp16:
// u32 index = (((ct*17+it)*4+g)*2+jp)*32 + lane)*4 + reg
__device__ __align__(16) uint32_t g_Wpk[32 * 17 * 4 * 2 * 32 * 4];
// proj weights fp16: [((rt*4+wr)*64+kc)][lane 32][reg 2] u32
__device__ __align__(16) uint32_t g_Whrpk[8 * 4 * 64 * 64];
// pair-packed fp16 activations: h [m][kc16][q8], hraw [m][kc64][q8], x [t][m][q8]
__device__ __align__(16) uint32_t g_hpk[(size_t)BB * 16 * 8];
__device__ __align__(16) uint32_t g_hrawpk[(size_t)BB * 64 * 8];
__device__ __align__(16) uint32_t g_xpk[(size_t)SS * BB * 8];

// ---------------- helpers ----------------
__device__ __forceinline__ float sigf(float x) { return 1.0f / (1.0f + __expf(-x)); }
__device__ __forceinline__ float tanh_f(float x) {
    float e = __expf(-2.0f * fabsf(x));
    float t = (1.0f - e) / (1.0f + e);
    return copysignf(t, x);
}
__device__ __forceinline__ uint32_t pack_h2(float e0, float e1) {
    __half2 h = __floats2half2_rn(e0, e1);
    return *reinterpret_cast<uint32_t*>(&h);
}
__device__ __forceinline__ void mma_f16(float* d, const uint32_t* a, uint32_t b0, uint32_t b1) {
    asm volatile("mma.sync.aligned.m16n8k16.row.col.f32.f16.f16.f32 "
                 "{%0,%1,%2,%3}, {%4,%5,%6,%7}, {%8,%9}, {%0,%1,%2,%3};"
                 : "+f"(d[0]), "+f"(d[1]), "+f"(d[2]), "+f"(d[3])
                 : "r"(a[0]), "r"(a[1]), "r"(a[2]), "r"(a[3]), "r"(b0), "r"(b1));
}
// deterministic per-m-group barrier: 32 arrivals, cumulative target
__device__ __forceinline__ void group_bar(int grp, unsigned int target) {
    __syncthreads();
    if (threadIdx.x == 0) {
        __threadfence();
        atomicAdd(&g_bar_cnt[grp * 32], 1u);
        while (atomicAdd(&g_bar_cnt[grp * 32], 0u) < target) { }
        __threadfence();
    }
    __syncthreads();
}

// ---------------- prologue 1: W_eff reduction -> fragment-packed (it=16), bias ----------------
__global__ __launch_bounds__(128) void prep_weff(
    const float* __restrict__ W_ih, const float* __restrict__ b_ih,
    const float* __restrict__ W_cmd, const float* __restrict__ b_cmd,
    const float* __restrict__ W_crd, const float* __restrict__ b_crd,
    const float* __restrict__ b_hh)
{
    int j = blockIdx.x;            // 0..4095 (gate-major row)
    int t = threadIdx.x;
    __shared__ float red[17][128];

    float acc[17];
#pragma unroll
    for (int c = 0; c < 17; c++) acc[c] = 0.0f;

    const float* wrow = W_ih + (size_t)j * DIN;
    for (int k = t; k < DD; k += 128) {
        float w = wrow[k];
#pragma unroll
        for (int c = 0; c < 10; c++) acc[c]      = fmaf(w, W_cmd[k * 10 + c], acc[c]);
#pragma unroll
        for (int c = 0; c < 6; c++)  acc[10 + c] = fmaf(w, W_crd[k * 6 + c], acc[10 + c]);
        acc[16] = fmaf(w, b_cmd[k] + b_crd[k], acc[16]);
    }
#pragma unroll
    for (int c = 0; c < 17; c++) red[c][t] = acc[c];
    __syncthreads();
    for (int off = 64; off > 0; off >>= 1) {
        if (t < off) {
#pragma unroll
            for (int c = 0; c < 17; c++) red[c][t] += red[c][t + off];
        }
        __syncthreads();
    }
    if (t == 0) {
        int g     = j >> 10;
        int jglob = j & 1023;
        int ct    = jglob >> 5;
        int rem   = jglob & 31;
        int nj    = rem >> 3;
        int l4    = rem & 7;
        int jp    = nj >> 1;
        int v     = nj & 1;
#pragma unroll
        for (int lq = 0; lq < 4; lq++) {
#pragma unroll
            for (int kh = 0; kh < 2; kh++) {
                size_t b4 = (size_t)((((ct * 17 + 16) * 4 + g) * 2 + jp) * 32 + (l4 * 4 + lq));
                size_t u = b4 * 4 + v * 2 + kh;
                g_Wpk[u] = pack_h2(red[2 * lq + 8 * kh][0], red[2 * lq + 8 * kh + 1][0]);
            }
        }
        g_bias[j] = red[16][0] + b_ih[j] + b_hh[j];
    }
}

// ---------------- prologue 2: Zc = ctx @ W_ih[:,1024:]^T + bias ----------------
__global__ __launch_bounds__(256) void prep_zc(
    const float* __restrict__ ctx, const float* __restrict__ W_ih)
{
    __shared__ float sA[64][17];
    __shared__ float sB[64][17];
    int n0 = blockIdx.x * 64;
    int m0 = blockIdx.y * 64;
    int tid = threadIdx.x;
    int tx = tid & 15;
    int ty = tid >> 4;

    float acc[4][4];
#pragma unroll
    for (int i = 0; i < 4; i++)
#pragma unroll
        for (int j = 0; j < 4; j++) acc[i][j] = 0.0f;

    for (int k0 = 0; k0 < 256; k0 += 16) {
        __syncthreads();
#pragma unroll
        for (int q = 0; q < 4; q++) {
            int e = q * 256 + tid;
            int r = e >> 4;
            int c = e & 15;
            sA[r][c] = ctx[(size_t)(m0 + r) * 256 + k0 + c];
            sB[r][c] = W_ih[(size_t)(n0 + r) * DIN + 1024 + k0 + c];
        }
        __syncthreads();
#pragma unroll
        for (int kk = 0; kk < 16; kk++) {
            float a[4];
            float b[4];
#pragma unroll
            for (int i = 0; i < 4; i++) a[i] = sA[ty + 16 * i][kk];
#pragma unroll
            for (int j = 0; j < 4; j++) b[j] = sB[tx + 16 * j][kk];
#pragma unroll
            for (int i = 0; i < 4; i++)
#pragma unroll
                for (int j = 0; j < 4; j++) acc[i][j] = fmaf(a[i], b[j], acc[i][j]);
        }
    }
#pragma unroll
    for (int i = 0; i < 4; i++) {
        int m = m0 + ty + 16 * i;
#pragma unroll
        for (int j = 0; j < 4; j++) {
            int n = n0 + tx + 16 * j;
            g_Zc[(size_t)m * G4 + n] = acc[i][j] + g_bias[n];
        }
    }
}

// ---------------- prologue 3: fragment-pack W_hh fp16 (it 0..15) ----------------
__global__ __launch_bounds__(256) void pack_whh(const float* __restrict__ W_hh)
{
    int idx = blockIdx.x * 256 + threadIdx.x;   // 0..131071
    int lane = idx & 31;
    int jp   = (idx >> 5) & 1;
    int g    = (idx >> 6) & 3;
    int it   = (idx >> 8) & 15;
    int ct   = idx >> 12;                       // 0..31
    uint32_t h4[4];
#pragma unroll
    for (int v = 0; v < 2; v++) {
        int nj = 2 * jp + v;
#pragma unroll
        for (int kh = 0; kh < 2; kh++) {
            int n = (g << 10) + ct * 32 + nj * 8 + (lane >> 2);
            int k = it * 16 + 2 * (lane & 3) + 8 * kh;
            h4[v * 2 + kh] = pack_h2(W_hh[(size_t)n * 256 + k], W_hh[(size_t)n * 256 + k + 1]);
        }
    }
    size_t base = (size_t)((((ct * 17 + it) * 4 + g) * 2 + jp) * 32 + lane) * 4;
    *(uint4*)&g_Wpk[base] = make_uint4(h4[0], h4[1], h4[2], h4[3]);
}

// ---------------- prologue 4: fragment-pack W_hr fp16 ----------------
__global__ __launch_bounds__(256) void pack_whr(const float* __restrict__ W_hr)
{
    int idx = blockIdx.x * 256 + threadIdx.x;   // 0..65535
    int lane = idx & 31;
    int kc = (idx >> 5) & 63;
    int wr = (idx >> 11) & 3;
    int rt = idx >> 13;
    uint32_t h2[2];
#pragma unroll
    for (int bh = 0; bh < 2; bh++) {
        int n = rt * 32 + wr * 8 + (lane >> 2);
        int k = kc * 16 + 2 * (lane & 3) + 8 * bh;
        h2[bh] = pack_h2(W_hr[(size_t)n * 1024 + k], W_hr[(size_t)n * 1024 + k + 1]);
    }
    size_t base = (size_t)((rt * 4 + wr) * 64 + kc) * 64 + lane * 2;
    *(uint2*)&g_Whrpk[base] = make_uint2(h2[0], h2[1]);
}

// ---------------- prologue 5: pair-pack x fp16 ----------------
__global__ __launch_bounds__(256) void pack_x(const float* __restrict__ x)
{
    int idx = blockIdx.x * 256 + threadIdx.x;   // 0..102399
    int m = idx & 511;
    int t = idx >> 9;
    const float* xr = x + ((size_t)m * SS + t) * 16;
    size_t base = ((size_t)t * 512 + m) * 8;
#pragma unroll
    for (int p = 0; p < 8; p++) {
        int q = (p < 4) ? 2 * p : 2 * (p - 4) + 1;
        g_xpk[base + q] = pack_h2(xr[2 * p], xr[2 * p + 1]);
    }
}

// ---------------- init (re-run every launch: determinism) ----------------
__global__ void init_state()
{
    int i = blockIdx.x * blockDim.x + threadIdx.x;
    if (i < 4 * 32) g_bar_cnt[i] = 0u;
    if (i < BB * 16 * 8) g_hpk[i] = 0u;
}

// ---------------- persistent-kernel phase helpers ----------------
__device__ __forceinline__ void g_loadA(uint2 aH[2], int it, int t, int m0, int wid, int l4, int lq)
{
#pragma unroll
    for (int h = 0; h < 2; h++) {
        int row = m0 + wid * 16 + h * 8 + l4;
        if (it < 16) {
            size_t off = ((size_t)row * 16 + it) * 8 + lq * 2;
            aH[h] = __ldcg((const uint2*)(g_hpk + off));
        } else {
            size_t off = ((size_t)t * 512 + row) * 8 + lq * 2;
            aH[h] = __ldcg((const uint2*)(g_xpk + off));
        }
    }
}
__device__ __forceinline__ void p_loadA(uint2 aH[2], int kc, int mbase, int l4, int lq)
{
#pragma unroll
    for (int h = 0; h < 2; h++) {
        int row = mbase + h * 8 + l4;
        size_t off = ((size_t)row * 64 + kc) * 8 + lq * 2;
        aH[h] = __ldcg((const uint2*)&g_hrawpk[off]);
    }
}

// ---------------- persistent recurrence ----------------
// gates map: 4 m-tiles (128 rows) x 32 col-tiles (32 j x 4 gates).
// smem: gates W slice (68KB) + proj W slice (64KB) + Zc tile (64KB). c state in registers.
// sync: per-m-group barriers (32 CTAs, closed dependency set for both phases).
__global__ __launch_bounds__(256, 1) void lstm_persistent()
{
    extern __shared__ uint32_t smemw[];
    uint32_t* sWg = smemw;                         // WG_U32
    uint32_t* sWp = smemw + WG_U32;                // WP_U32
    float*    sZc = (float*)(smemw + WG_U32 + WP_U32); // ZC_F32

    int bid = blockIdx.x;
    // gates tile map
    int ct = bid & 31;
    int mt = bid >> 5;          // m-group (also the barrier group)
    int m0 = mt * 128;
    // proj tile map
    int rt2 = bid & 7;
    int mt2 = bid >> 3;

    int tid = threadIdx.x;
    int wid = tid >> 5;
    int lane = tid & 31;
    int l4 = lane >> 2;
    int lq = lane & 3;

    // ---- one-time staging: weight slices + Zc tile into smem ----
    {
        const uint4* srcg = (const uint4*)(g_Wpk + (size_t)ct * WG_U32);
        uint4* dstg = (uint4*)sWg;
        for (int i = tid; i < WG_U32 / 4; i += 256) dstg[i] = srcg[i];
        const uint4* srcp = (const uint4*)(g_Whrpk + (size_t)rt2 * WP_U32);
        uint4* dstp = (uint4*)sWp;
        for (int i = tid; i < WP_U32 / 4; i += 256) dstp[i] = srcp[i];
    }
    for (int idx = tid; idx < 128 * 128; idx += 256) {
        int ml = idx >> 7;
        int col = idx & 127;
        int g = col >> 5;
        int jl = col & 31;
        sZc[idx] = g_Zc[(size_t)(m0 + ml) * G4 + (g << 10) + ct * 32 + jl];
    }
    // cell state in registers: creg[h][nj][0/1] for this thread's fixed (m,j) coords
    float creg[2][4][2];
#pragma unroll
    for (int h = 0; h < 2; h++)
#pragma unroll
        for (int nj = 0; nj < 4; nj++) {
            creg[h][nj][0] = 0.0f;
            creg[h][nj][1] = 0.0f;
        }
    __syncthreads();

    unsigned int bar = 0;

    for (int t = 0; t < SS; t++) {
        // ================= gates phase =================
        {
            float acc[4][4][4];
#pragma unroll
            for (int g = 0; g < 4; g++)
#pragma unroll
                for (int nj = 0; nj < 4; nj++)
#pragma unroll
                    for (int q = 0; q < 4; q++) acc[g][nj][q] = 0.0f;

            // 4-deep A prefetch pipeline
            uint2 aB[4][2];
#pragma unroll
            for (int p = 0; p < 4; p++) g_loadA(aB[p], p, t, m0, wid, l4, lq);
#pragma unroll
            for (int it = 0; it < 17; ++it) {
                uint32_t AH[4] = { aB[it & 3][0].x, aB[it & 3][1].x,
                                   aB[it & 3][0].y, aB[it & 3][1].y };
                if (it + 4 < 17) g_loadA(aB[it & 3], it + 4, t, m0, wid, l4, lq);
#pragma unroll
                for (int g = 0; g < 4; g++) {
#pragma unroll
                    for (int jp = 0; jp < 2; jp++) {
                        uint4 h4 = *(const uint4*)&sWg[((((it * 4 + g) * 2 + jp) * 32 + lane)) * 4];
                        mma_f16(acc[g][2 * jp + 0], AH, h4.x, h4.y);
                        mma_f16(acc[g][2 * jp + 1], AH, h4.z, h4.w);
                    }
                }
            }

            // epilogue: + Zc(smem), LSTM cell (c in regs), write pair-packed hraw
#pragma unroll
            for (int h = 0; h < 2; h++) {
                int ml = wid * 16 + h * 8 + l4;
                int m = m0 + ml;
#pragma unroll
                for (int nj = 0; nj < 4; nj++) {
                    int jl = nj * 8 + 2 * lq;
                    float pre0[4], pre1[4];
#pragma unroll
                    for (int g = 0; g < 4; g++) {
                        float2 zc = *(const float2*)&sZc[ml * 128 + g * 32 + jl];
                        pre0[g] = acc[g][nj][2 * h + 0] + zc.x;
                        pre1[g] = acc[g][nj][2 * h + 1] + zc.y;
                    }
                    float cn0 = sigf(pre0[1]) * creg[h][nj][0] + sigf(pre0[0]) * tanh_f(pre0[2]);
                    float cn1 = sigf(pre1[1]) * creg[h][nj][1] + sigf(pre1[0]) * tanh_f(pre1[2]);
                    creg[h][nj][0] = cn0;
                    creg[h][nj][1] = cn1;
                    float hr0 = sigf(pre0[3]) * tanh_f(cn0);
                    float hr1 = sigf(pre1[3]) * tanh_f(cn1);
                    int q = 2 * lq + (nj & 1);
                    int kc = ct * 2 + (nj >> 1);
                    g_hrawpk[((size_t)m * 64 + kc) * 8 + q] = pack_h2(hr0, hr1);
                }
            }
        }
        group_bar(mt, ++bar * NGRP);

        // ================= projection phase =================
        {
            int wm = wid >> 2;
            int wr = wid & 3;
            int mbase = mt2 * 32 + wm * 16;

            float acc[4] = {0.0f, 0.0f, 0.0f, 0.0f};
            // 4-deep A prefetch pipeline
            uint2 aB[4][2];
#pragma unroll
            for (int p = 0; p < 4; p++) p_loadA(aB[p], p, mbase, l4, lq);
#pragma unroll 8
            for (int kc = 0; kc < 64; ++kc) {
                uint32_t AH[4] = { aB[kc & 3][0].x, aB[kc & 3][1].x,
                                   aB[kc & 3][0].y, aB[kc & 3][1].y };
                if (kc + 4 < 64) p_loadA(aB[kc & 3], kc + 4, mbase, l4, lq);
                uint2 bh = *(const uint2*)&sWp[(wr * 64 + kc) * 64 + lane * 2];
                mma_f16(acc, AH, bh.x, bh.y);
            }

            int r = rt2 * 32 + wr * 8 + 2 * lq;
            int kc_h = rt2 * 2 + (wr >> 1);
            int q = 2 * lq + (wr & 1);
#pragma unroll
            for (int h = 0; h < 2; h++) {
                int m = mbase + h * 8 + l4;
                float v0 = acc[2 * h + 0];
                float v1 = acc[2 * h + 1];
                *(float2*)&g_hs[((size_t)m * SS + t) * PP + r] = make_float2(v0, v1);
                g_hpk[((size_t)m * 16 + kc_h) * 8 + q] = pack_h2(v0, v1);
            }
        }
        group_bar(mt, ++bar * NGRP);
    }
}

// ---------------- output heads: LN + command logits + coords (warp per row) ----------------
__global__ __launch_bounds__(256) void head_kernel(
    const float* __restrict__ ln_g, const float* __restrict__ ln_b,
    const float* __restrict__ W_oc, const float* __restrict__ b_oc,
    const float* __restrict__ W_ox, const float* __restrict__ b_ox,
    const float* __restrict__ scale_p, float* __restrict__ out)
{
    int gw = (blockIdx.x * 256 + threadIdx.x) >> 5;
    int lane = threadIdx.x & 31;
    if (gw >= BB * SS) return;

    const float* hrow = g_hs + (size_t)gw * PP;
    float v[8];
#pragma unroll
    for (int q = 0; q < 2; q++) {
        float4 f = *reinterpret_cast<const float4*>(hrow + lane * 8 + q * 4);
        v[q * 4 + 0] = f.x;
        v[q * 4 + 1] = f.y;
        v[q * 4 + 2] = f.z;
        v[q * 4 + 3] = f.w;
    }
    float s = 0.0f;
    float s2 = 0.0f;
#pragma unroll
    for (int e = 0; e < 8; e++) {
        s += v[e];
        s2 = fmaf(v[e], v[e], s2);
    }
#pragma unroll
    for (int o = 16; o > 0; o >>= 1) {
        s  += __shfl_xor_sync(0xFFFFFFFFu, s, o);
        s2 += __shfl_xor_sync(0xFFFFFFFFu, s2, o);
    }
    float mean = s * (1.0f / 256.0f);
    float var = s2 * (1.0f / 256.0f) - mean * mean;
    float rstd = rsqrtf(var + 1e-5f);

    float hn[8];
#pragma unroll
    for (int e = 0; e < 8; e++) {
        int c = lane * 8 + e;
        hn[e] = (v[e] - mean) * rstd * ln_g[c] + ln_b[c];
    }

    float lgs[10];
#pragma unroll
    for (int cc = 0; cc < 10; cc++) {
        float p = 0.0f;
#pragma unroll
        for (int e = 0; e < 8; e++)
            p = fmaf(hn[e], W_oc[cc * 256 + lane * 8 + e], p);
#pragma unroll
        for (int o = 16; o > 0; o >>= 1) p += __shfl_xor_sync(0xFFFFFFFFu, p, o);
        p += b_oc[cc];
        lgs[cc] = p;
        if (lane == cc) out[(size_t)gw * 10 + cc] = p;
    }

    float csc = *scale_p;
    float* outc = out + (size_t)BB * SS * 10;
#pragma unroll
    for (int q = 0; q < 6; q++) {
        float p = 0.0f;
#pragma unroll
        for (int e = 0; e < 8; e++)
            p = fmaf(hn[e], W_ox[q * 266 + lane * 8 + e], p);
#pragma unroll
        for (int o = 16; o > 0; o >>= 1) p += __shfl_xor_sync(0xFFFFFFFFu, p, o);
#pragma unroll
        for (int cc = 0; cc < 10; cc++)
            p = fmaf(lgs[cc], W_ox[q * 266 + 256 + cc], p);
        p += b_ox[q];
        float z = tanh_f(p * csc);
        if (lane == q) outc[(size_t)gw * 6 + q] = z;
    }
}

// ---------------- launch ----------------
extern "C" void kernel_launch(void* const* d_in, const int* in_sizes, int n_in,
                              void* d_out, int out_size)
{
    const float* x      = (const float*)d_in[0];
    const float* ctx    = (const float*)d_in[1];
    const float* W_cmd  = (const float*)d_in[2];
    const float* b_cmd  = (const float*)d_in[3];
    const float* W_crd  = (const float*)d_in[4];
    const float* b_crd  = (const float*)d_in[5];
    const float* W_ih   = (const float*)d_in[6];
    const float* b_ih   = (const float*)d_in[7];
    const float* W_hh   = (const float*)d_in[8];
    const float* b_hh   = (const float*)d_in[9];
    const float* W_hr   = (const float*)d_in[10];
    const float* ln_g   = (const float*)d_in[11];
    const float* ln_b   = (const float*)d_in[12];
    const float* W_oc   = (const float*)d_in[13];
    const float* b_oc   = (const float*)d_in[14];
    const float* W_ox   = (const float*)d_in[15];
    const float* b_ox   = (const float*)d_in[16];
    const float* cscale = (const float*)d_in[17];
    float* out = (float*)d_out;

    static bool attr_set = false;
    if (!attr_set) {
        cudaFuncSetAttribute(lstm_persistent,
                             cudaFuncAttributeMaxDynamicSharedMemorySize,
                             SMEM_BYTES);
        attr_set = true;
    }

    prep_weff<<<G4, 128>>>(W_ih, b_ih, W_cmd, b_cmd, W_crd, b_crd, b_hh);
    prep_zc<<<dim3(G4 / 64, BB / 64), 256>>>(ctx, W_ih);
    pack_whh<<<512, 256>>>(W_hh);
    pack_whr<<<256, 256>>>(W_hr);
    pack_x<<<400, 256>>>(x);
    init_state<<<(BB * 16 * 8 + 255) / 256, 256>>>();

    lstm_persistent<<<NCTA, 256, SMEM_BYTES>>>();

    head_kernel<<<(BB * SS * 32 + 255) / 256, 256>>>(
        ln_g, ln_b, W_oc, b_oc, W_ox, b_ox, cscale, out);
}

// round 13
// speedup vs baseline: 1.2107x; 1.2107x over previous
#include <cuda_runtime.h>
#include <cuda_fp16.h>
#include <cstdint>
#include <math.h>

#define BB   512
#define SS   200
#define DD   1024
#define PP   256
#define G4   4096
#define DIN  1280
#define NCTA 128

#define WG_U32 17408   // gates weight slice per CTA in u32 (17*4*2*32*4)
#define WP_U32 16384   // proj weight slice per CTA in u32 (4*64*64)
#define ZC_F32 16384   // Zc tile (128 x 128)
#define SMEM_BYTES ((WG_U32 + WP_U32) * 4 + ZC_F32 * 4)

// ---------------- scratch (device globals; no allocation allowed) ----------------
__device__ float g_bias[G4];                       // folded bias
__device__ float g_Zc[(size_t)BB * G4];            // (512,4096) context+bias
__device__ float g_hs[(size_t)BB * SS * PP];       // all projected hiddens (heads)
__device__ unsigned int g_bar_count;               // grid barrier (cumulative)

// gates weights, fragment-packed fp16:
// u32 index = (((ct*17+it)*4+g)*2+jp)*32 + lane)*4 + reg
__device__ __align__(16) uint32_t g_Wpk[32 * 17 * 4 * 2 * 32 * 4];
// proj weights fp16: [((rt*4+wr)*64+kc)][lane 32][reg 2] u32
__device__ __align__(16) uint32_t g_Whrpk[8 * 4 * 64 * 64];
// pair-packed fp16 activations: h [m][kc16][q8], hraw [m][kc64][q8], x [t][m][q8]
__device__ __align__(16) uint32_t g_hpk[(size_t)BB * 16 * 8];
__device__ __align__(16) uint32_t g_hrawpk[(size_t)BB * 64 * 8];
__device__ __align__(16) uint32_t g_xpk[(size_t)SS * BB * 8];

// ---------------- helpers ----------------
__device__ __forceinline__ float sigf(float x) {
    float e = __expf(-x);
    return __fdividef(1.0f, 1.0f + e);
}
__device__ __forceinline__ float tanh_f(float x) {
    float e = __expf(-2.0f * fabsf(x));
    float t = __fdividef(1.0f - e, 1.0f + e);
    return copysignf(t, x);
}
__device__ __forceinline__ uint32_t pack_h2(float e0, float e1) {
    __half2 h = __floats2half2_rn(e0, e1);
    return *reinterpret_cast<uint32_t*>(&h);
}
__device__ __forceinline__ void mma_f16(float* d, const uint32_t* a, uint32_t b0, uint32_t b1) {
    asm volatile("mma.sync.aligned.m16n8k16.row.col.f32.f16.f16.f32 "
                 "{%0,%1,%2,%3}, {%4,%5,%6,%7}, {%8,%9}, {%0,%1,%2,%3};"
                 : "+f"(d[0]), "+f"(d[1]), "+f"(d[2]), "+f"(d[3])
                 : "r"(a[0]), "r"(a[1]), "r"(a[2]), "r"(a[3]), "r"(b0), "r"(b1));
}
// deterministic grid barrier: cumulative counter, target = bar_id * NCTA
__device__ __forceinline__ void grid_bar(unsigned int target) {
    __syncthreads();
    if (threadIdx.x == 0) {
        __threadfence();
        atomicAdd(&g_bar_count, 1u);
        while (atomicAdd(&g_bar_count, 0u) < target) { }
        __threadfence();
    }
    __syncthreads();
}

// ---------------- prologue 1: W_eff reduction -> fragment-packed (it=16), bias ----------------
__global__ __launch_bounds__(128) void prep_weff(
    const float* __restrict__ W_ih, const float* __restrict__ b_ih,
    const float* __restrict__ W_cmd, const float* __restrict__ b_cmd,
    const float* __restrict__ W_crd, const float* __restrict__ b_crd,
    const float* __restrict__ b_hh)
{
    int j = blockIdx.x;            // 0..4095 (gate-major row)
    int t = threadIdx.x;
    __shared__ float red[17][128];

    float acc[17];
#pragma unroll
    for (int c = 0; c < 17; c++) acc[c] = 0.0f;

    const float* wrow = W_ih + (size_t)j * DIN;
    for (int k = t; k < DD; k += 128) {
        float w = wrow[k];
#pragma unroll
        for (int c = 0; c < 10; c++) acc[c]      = fmaf(w, W_cmd[k * 10 + c], acc[c]);
#pragma unroll
        for (int c = 0; c < 6; c++)  acc[10 + c] = fmaf(w, W_crd[k * 6 + c], acc[10 + c]);
        acc[16] = fmaf(w, b_cmd[k] + b_crd[k], acc[16]);
    }
#pragma unroll
    for (int c = 0; c < 17; c++) red[c][t] = acc[c];
    __syncthreads();
    for (int off = 64; off > 0; off >>= 1) {
        if (t < off) {
#pragma unroll
            for (int c = 0; c < 17; c++) red[c][t] += red[c][t + off];
        }
        __syncthreads();
    }
    if (t == 0) {
        int g     = j >> 10;
        int jglob = j & 1023;
        int ct    = jglob >> 5;
        int rem   = jglob & 31;
        int nj    = rem >> 3;
        int l4    = rem & 7;
        int jp    = nj >> 1;
        int v     = nj & 1;
#pragma unroll
        for (int lq = 0; lq < 4; lq++) {
#pragma unroll
            for (int kh = 0; kh < 2; kh++) {
                size_t b4 = (size_t)((((ct * 17 + 16) * 4 + g) * 2 + jp) * 32 + (l4 * 4 + lq));
                size_t u = b4 * 4 + v * 2 + kh;
                g_Wpk[u] = pack_h2(red[2 * lq + 8 * kh][0], red[2 * lq + 8 * kh + 1][0]);
            }
        }
        g_bias[j] = red[16][0] + b_ih[j] + b_hh[j];
    }
}

// ---------------- prologue 2: Zc = ctx @ W_ih[:,1024:]^T + bias ----------------
__global__ __launch_bounds__(256) void prep_zc(
    const float* __restrict__ ctx, const float* __restrict__ W_ih)
{
    __shared__ float sA[64][17];
    __shared__ float sB[64][17];
    int n0 = blockIdx.x * 64;
    int m0 = blockIdx.y * 64;
    int tid = threadIdx.x;
    int tx = tid & 15;
    int ty = tid >> 4;

    float acc[4][4];
#pragma unroll
    for (int i = 0; i < 4; i++)
#pragma unroll
        for (int j = 0; j < 4; j++) acc[i][j] = 0.0f;

    for (int k0 = 0; k0 < 256; k0 += 16) {
        __syncthreads();
#pragma unroll
        for (int q = 0; q < 4; q++) {
            int e = q * 256 + tid;
            int r = e >> 4;
            int c = e & 15;
            sA[r][c] = ctx[(size_t)(m0 + r) * 256 + k0 + c];
            sB[r][c] = W_ih[(size_t)(n0 + r) * DIN + 1024 + k0 + c];
        }
        __syncthreads();
#pragma unroll
        for (int kk = 0; kk < 16; kk++) {
            float a[4];
            float b[4];
#pragma unroll
            for (int i = 0; i < 4; i++) a[i] = sA[ty + 16 * i][kk];
#pragma unroll
            for (int j = 0; j < 4; j++) b[j] = sB[tx + 16 * j][kk];
#pragma unroll
            for (int i = 0; i < 4; i++)
#pragma unroll
                for (int j = 0; j < 4; j++) acc[i][j] = fmaf(a[i], b[j], acc[i][j]);
        }
    }
#pragma unroll
    for (int i = 0; i < 4; i++) {
        int m = m0 + ty + 16 * i;
#pragma unroll
        for (int j = 0; j < 4; j++) {
            int n = n0 + tx + 16 * j;
            g_Zc[(size_t)m * G4 + n] = acc[i][j] + g_bias[n];
        }
    }
}

// ---------------- prologue 3 (merged): pack W_hh, W_hr, x; init barrier + h ----------------
// block ranges: [0,512) whh | [512,768) whr | [768,1168) x | [1168,1424) init
__global__ __launch_bounds__(256) void pack_all(
    const float* __restrict__ W_hh, const float* __restrict__ W_hr,
    const float* __restrict__ x)
{
    int b = blockIdx.x;
    if (b < 512) {
        int idx = b * 256 + threadIdx.x;        // 0..131071
        int lane = idx & 31;
        int jp   = (idx >> 5) & 1;
        int g    = (idx >> 6) & 3;
        int it   = (idx >> 8) & 15;
        int ct   = idx >> 12;                   // 0..31
        uint32_t h4[4];
#pragma unroll
        for (int v = 0; v < 2; v++) {
            int nj = 2 * jp + v;
#pragma unroll
            for (int kh = 0; kh < 2; kh++) {
                int n = (g << 10) + ct * 32 + nj * 8 + (lane >> 2);
                int k = it * 16 + 2 * (lane & 3) + 8 * kh;
                h4[v * 2 + kh] = pack_h2(W_hh[(size_t)n * 256 + k], W_hh[(size_t)n * 256 + k + 1]);
            }
        }
        size_t base = (size_t)((((ct * 17 + it) * 4 + g) * 2 + jp) * 32 + lane) * 4;
        *(uint4*)&g_Wpk[base] = make_uint4(h4[0], h4[1], h4[2], h4[3]);
    } else if (b < 768) {
        int idx = (b - 512) * 256 + threadIdx.x; // 0..65535
        int lane = idx & 31;
        int kc = (idx >> 5) & 63;
        int wr = (idx >> 11) & 3;
        int rt = idx >> 13;
        uint32_t h2[2];
#pragma unroll
        for (int bh = 0; bh < 2; bh++) {
            int n = rt * 32 + wr * 8 + (lane >> 2);
            int k = kc * 16 + 2 * (lane & 3) + 8 * bh;
            h2[bh] = pack_h2(W_hr[(size_t)n * 1024 + k], W_hr[(size_t)n * 1024 + k + 1]);
        }
        size_t base = (size_t)((rt * 4 + wr) * 64 + kc) * 64 + lane * 2;
        *(uint2*)&g_Whrpk[base] = make_uint2(h2[0], h2[1]);
    } else if (b < 1168) {
        int idx = (b - 768) * 256 + threadIdx.x; // 0..102399
        int m = idx & 511;
        int t = idx >> 9;
        const float* xr = x + ((size_t)m * SS + t) * 16;
        size_t base = ((size_t)t * 512 + m) * 8;
#pragma unroll
        for (int p = 0; p < 8; p++) {
            int q = (p < 4) ? 2 * p : 2 * (p - 4) + 1;
            g_xpk[base + q] = pack_h2(xr[2 * p], xr[2 * p + 1]);
        }
    } else {
        int i = (b - 1168) * 256 + threadIdx.x;  // 0..65535
        if (i == 0) g_bar_count = 0u;
        if (i < BB * 16 * 8) g_hpk[i] = 0u;
    }
}

// ---------------- persistent-kernel phase helpers ----------------
__device__ __forceinline__ void g_loadA(uint2 aH[2], int it, int t, int m0, int wid, int l4, int lq)
{
#pragma unroll
    for (int h = 0; h < 2; h++) {
        int row = m0 + wid * 16 + h * 8 + l4;
        if (it < 16) {
            size_t off = ((size_t)row * 16 + it) * 8 + lq * 2;
            aH[h] = __ldcg((const uint2*)(g_hpk + off));
        } else {
            size_t off = ((size_t)t * 512 + row) * 8 + lq * 2;
            aH[h] = __ldcg((const uint2*)(g_xpk + off));
        }
    }
}
__device__ __forceinline__ void p_loadA(uint2 aH[2], int kc, int mbase, int l4, int lq)
{
#pragma unroll
    for (int h = 0; h < 2; h++) {
        int row = mbase + h * 8 + l4;
        size_t off = ((size_t)row * 64 + kc) * 8 + lq * 2;
        aH[h] = __ldcg((const uint2*)&g_hrawpk[off]);
    }
}

// ---------------- persistent recurrence ----------------
// gates map: 4 m-tiles (128 rows) x 32 col-tiles (32 j x 4 gates).
// smem: gates W slice (68KB) + proj W slice (64KB) + Zc tile (64KB). c state in registers.
__global__ __launch_bounds__(256, 1) void lstm_persistent()
{
    extern __shared__ uint32_t smemw[];
    uint32_t* sWg = smemw;                         // WG_U32
    uint32_t* sWp = smemw + WG_U32;                // WP_U32
    float*    sZc = (float*)(smemw + WG_U32 + WP_U32); // ZC_F32

    int bid = blockIdx.x;
    // gates tile map
    int ct = bid & 31;
    int mt = bid >> 5;
    int m0 = mt * 128;
    // proj tile map
    int rt2 = bid & 7;
    int mt2 = bid >> 3;

    int tid = threadIdx.x;
    int wid = tid >> 5;
    int lane = tid & 31;
    int l4 = lane >> 2;
    int lq = lane & 3;

    // ---- one-time staging: weight slices + Zc tile into smem ----
    {
        const uint4* srcg = (const uint4*)(g_Wpk + (size_t)ct * WG_U32);
        uint4* dstg = (uint4*)sWg;
        for (int i = tid; i < WG_U32 / 4; i += 256) dstg[i] = srcg[i];
        const uint4* srcp = (const uint4*)(g_Whrpk + (size_t)rt2 * WP_U32);
        uint4* dstp = (uint4*)sWp;
        for (int i = tid; i < WP_U32 / 4; i += 256) dstp[i] = srcp[i];
    }
    for (int idx = tid; idx < 128 * 128; idx += 256) {
        int ml = idx >> 7;
        int col = idx & 127;
        int g = col >> 5;
        int jl = col & 31;
        sZc[idx] = g_Zc[(size_t)(m0 + ml) * G4 + (g << 10) + ct * 32 + jl];
    }
    // cell state in registers: creg[h][nj][0/1] for this thread's fixed (m,j) coords
    float creg[2][4][2];
#pragma unroll
    for (int h = 0; h < 2; h++)
#pragma unroll
        for (int nj = 0; nj < 4; nj++) {
            creg[h][nj][0] = 0.0f;
            creg[h][nj][1] = 0.0f;
        }
    __syncthreads();

    unsigned int bar = 0;

    for (int t = 0; t < SS; t++) {
        // ================= gates phase =================
        {
            float acc[4][4][4];
#pragma unroll
            for (int g = 0; g < 4; g++)
#pragma unroll
                for (int nj = 0; nj < 4; nj++)
#pragma unroll
                    for (int q = 0; q < 4; q++) acc[g][nj][q] = 0.0f;

            uint2 aH0[2], aH1[2];
            g_loadA(aH0, 0, t, m0, wid, l4, lq);
#pragma unroll
            for (int it = 0; it < 17; ++it) {
                if (it + 1 < 17) g_loadA(aH1, it + 1, t, m0, wid, l4, lq);
                uint32_t AH[4] = { aH0[0].x, aH0[1].x, aH0[0].y, aH0[1].y };
#pragma unroll
                for (int g = 0; g < 4; g++) {
#pragma unroll
                    for (int jp = 0; jp < 2; jp++) {
                        uint4 h4 = *(const uint4*)&sWg[((((it * 4 + g) * 2 + jp) * 32 + lane)) * 4];
                        mma_f16(acc[g][2 * jp + 0], AH, h4.x, h4.y);
                        mma_f16(acc[g][2 * jp + 1], AH, h4.z, h4.w);
                    }
                }
                aH0[0] = aH1[0];
                aH0[1] = aH1[1];
            }

            // epilogue: + Zc(smem), LSTM cell (c in regs), write pair-packed hraw
#pragma unroll
            for (int h = 0; h < 2; h++) {
                int ml = wid * 16 + h * 8 + l4;
                int m = m0 + ml;
#pragma unroll
                for (int nj = 0; nj < 4; nj++) {
                    int jl = nj * 8 + 2 * lq;
                    float pre0[4], pre1[4];
#pragma unroll
                    for (int g = 0; g < 4; g++) {
                        float2 zc = *(const float2*)&sZc[ml * 128 + g * 32 + jl];
                        pre0[g] = acc[g][nj][2 * h + 0] + zc.x;
                        pre1[g] = acc[g][nj][2 * h + 1] + zc.y;
                    }
                    float cn0 = sigf(pre0[1]) * creg[h][nj][0] + sigf(pre0[0]) * tanh_f(pre0[2]);
                    float cn1 = sigf(pre1[1]) * creg[h][nj][1] + sigf(pre1[0]) * tanh_f(pre1[2]);
                    creg[h][nj][0] = cn0;
                    creg[h][nj][1] = cn1;
                    float hr0 = sigf(pre0[3]) * tanh_f(cn0);
                    float hr1 = sigf(pre1[3]) * tanh_f(cn1);
                    int q = 2 * lq + (nj & 1);
                    int kc = ct * 2 + (nj >> 1);
                    g_hrawpk[((size_t)m * 64 + kc) * 8 + q] = pack_h2(hr0, hr1);
                }
            }
        }
        grid_bar(++bar * NCTA);

        // ================= projection phase =================
        {
            int wm = wid >> 2;
            int wr = wid & 3;
            int mbase = mt2 * 32 + wm * 16;

            float acc[4] = {0.0f, 0.0f, 0.0f, 0.0f};
            uint2 aH0[2], aH1[2];
            p_loadA(aH0, 0, mbase, l4, lq);
#pragma unroll 8
            for (int kc = 0; kc < 64; ++kc) {
                if (kc + 1 < 64) p_loadA(aH1, kc + 1, mbase, l4, lq);
                uint32_t AH[4] = { aH0[0].x, aH0[1].x, aH0[0].y, aH0[1].y };
                uint2 bh = *(const uint2*)&sWp[(wr * 64 + kc) * 64 + lane * 2];
                mma_f16(acc, AH, bh.x, bh.y);
                aH0[0] = aH1[0];
                aH0[1] = aH1[1];
            }

            int r = rt2 * 32 + wr * 8 + 2 * lq;
            int kc_h = rt2 * 2 + (wr >> 1);
            int q = 2 * lq + (wr & 1);
#pragma unroll
            for (int h = 0; h < 2; h++) {
                int m = mbase + h * 8 + l4;
                float v0 = acc[2 * h + 0];
                float v1 = acc[2 * h + 1];
                *(float2*)&g_hs[((size_t)m * SS + t) * PP + r] = make_float2(v0, v1);
                g_hpk[((size_t)m * 16 + kc_h) * 8 + q] = pack_h2(v0, v1);
            }
        }
        grid_bar(++bar * NCTA);
    }
}

// ---------------- output heads: LN + command logits + coords (warp per row) ----------------
__global__ __launch_bounds__(256) void head_kernel(
    const float* __restrict__ ln_g, const float* __restrict__ ln_b,
    const float* __restrict__ W_oc, const float* __restrict__ b_oc,
    const float* __restrict__ W_ox, const float* __restrict__ b_ox,
    const float* __restrict__ scale_p, float* __restrict__ out)
{
    int gw = (blockIdx.x * 256 + threadIdx.x) >> 5;
    int lane = threadIdx.x & 31;
    if (gw >= BB * SS) return;

    const float* hrow = g_hs + (size_t)gw * PP;
    float v[8];
#pragma unroll
    for (int q = 0; q < 2; q++) {
        float4 f = *reinterpret_cast<const float4*>(hrow + lane * 8 + q * 4);
        v[q * 4 + 0] = f.x;
        v[q * 4 + 1] = f.y;
        v[q * 4 + 2] = f.z;
        v[q * 4 + 3] = f.w;
    }
    float s = 0.0f;
    float s2 = 0.0f;
#pragma unroll
    for (int e = 0; e < 8; e++) {
        s += v[e];
        s2 = fmaf(v[e], v[e], s2);
    }
#pragma unroll
    for (int o = 16; o > 0; o >>= 1) {
        s  += __shfl_xor_sync(0xFFFFFFFFu, s, o);
        s2 += __shfl_xor_sync(0xFFFFFFFFu, s2, o);
    }
    float mean = s * (1.0f / 256.0f);
    float var = s2 * (1.0f / 256.0f) - mean * mean;
    float rstd = rsqrtf(var + 1e-5f);

    float hn[8];
#pragma unroll
    for (int e = 0; e < 8; e++) {
        int c = lane * 8 + e;
        hn[e] = (v[e] - mean) * rstd * ln_g[c] + ln_b[c];
    }

    float lgs[10];
#pragma unroll
    for (int cc = 0; cc < 10; cc++) {
        float p = 0.0f;
#pragma unroll
        for (int e = 0; e < 8; e++)
            p = fmaf(hn[e], W_oc[cc * 256 + lane * 8 + e], p);
#pragma unroll
        for (int o = 16; o > 0; o >>= 1) p += __shfl_xor_sync(0xFFFFFFFFu, p, o);
        p += b_oc[cc];
        lgs[cc] = p;
        if (lane == cc) out[(size_t)gw * 10 + cc] = p;
    }

    float csc = *scale_p;
    float* outc = out + (size_t)BB * SS * 10;
#pragma unroll
    for (int q = 0; q < 6; q++) {
        float p = 0.0f;
#pragma unroll
        for (int e = 0; e < 8; e++)
            p = fmaf(hn[e], W_ox[q * 266 + lane * 8 + e], p);
#pragma unroll
        for (int o = 16; o > 0; o >>= 1) p += __shfl_xor_sync(0xFFFFFFFFu, p, o);
#pragma unroll
        for (int cc = 0; cc < 10; cc++)
            p = fmaf(lgs[cc], W_ox[q * 266 + 256 + cc], p);
        p += b_ox[q];
        float z = tanh_f(p * csc);
        if (lane == q) outc[(size_t)gw * 6 + q] = z;
    }
}

// ---------------- launch ----------------
extern "C" void kernel_launch(void* const* d_in, const int* in_sizes, int n_in,
                              void* d_out, int out_size)
{
    const float* x      = (const float*)d_in[0];
    const float* ctx    = (const float*)d_in[1];
    const float* W_cmd  = (const float*)d_in[2];
    const float* b_cmd  = (const float*)d_in[3];
    const float* W_crd  = (const float*)d_in[4];
    const float* b_crd  = (const float*)d_in[5];
    const float* W_ih   = (const float*)d_in[6];
    const float* b_ih   = (const float*)d_in[7];
    const float* W_hh   = (const float*)d_in[8];
    const float* b_hh   = (const float*)d_in[9];
    const float* W_hr   = (const float*)d_in[10];
    const float* ln_g   = (const float*)d_in[11];
    const float* ln_b   = (const float*)d_in[12];
    const float* W_oc   = (const float*)d_in[13];
    const float* b_oc   = (const float*)d_in[14];
    const float* W_ox   = (const float*)d_in[15];
    const float* b_ox   = (const float*)d_in[16];
    const float* cscale = (const float*)d_in[17];
    float* out = (float*)d_out;

    static bool attr_set = false;
    if (!attr_set) {
        cudaFuncSetAttribute(lstm_persistent,
                             cudaFuncAttributeMaxDynamicSharedMemorySize,
                             SMEM_BYTES);
        attr_set = true;
    }

    prep_weff<<<G4, 128>>>(W_ih, b_ih, W_cmd, b_cmd, W_crd, b_crd, b_hh);
    prep_zc<<<dim3(G4 / 64, BB / 64), 256>>>(ctx, W_ih);
    pack_all<<<1424, 256>>>(W_hh, W_hr, x);

    lstm_persistent<<<NCTA, 256, SMEM_BYTES>>>();

    head_kernel<<<(BB * SS * 32 + 255) / 256, 256>>>(
        ln_g, ln_b, W_oc, b_oc, W_ox, b_ox, cscale, out);
}